// round 1
// baseline (speedup 1.0000x reference)
#include <cuda_runtime.h>

// Problem constants
#define BB   4
#define TT   2048
#define CC   1024
#define HH   16
#define HD   64
#define MR   (BB*TT)        // 8192 rows

// Scratch (device globals: allocation-free, graph-capturable)
__device__ float g_qkv[(size_t)MR * 3 * CC];   // [B*T, 3C]
__device__ float g_y[(size_t)MR * CC];         // [B*T, C] attention output

// ---------------------------------------------------------------------------
// SGEMM: C[M,N] = A[M,K] @ B[K,N] + bias[N]
// 128x128 block, BK=8, 8x8 per thread, 256 threads
// ---------------------------------------------------------------------------
__global__ __launch_bounds__(256, 2)
void sgemm_bias(const float* __restrict__ A, const float* __restrict__ B,
                const float* __restrict__ bias, float* __restrict__ C,
                int M, int N, int K)
{
    __shared__ float As[8][128];   // transposed A tile: As[k][m]
    __shared__ float Bs[8][128];   // Bs[k][n]

    const int tid  = threadIdx.x;
    const int trow = tid >> 4;        // 0..15
    const int tcol = tid & 15;        // 0..15
    const int aRow = tid >> 1;        // 0..127
    const int aCol = (tid & 1) << 2;  // 0 or 4
    const int bRow = tid >> 5;        // 0..7
    const int bCol = (tid & 31) << 2; // 0..124

    const float* Ag = A + (size_t)(blockIdx.y * 128 + aRow) * K + aCol;
    const float* Bg = B + (size_t)bRow * N + blockIdx.x * 128 + bCol;

    float acc[8][8];
#pragma unroll
    for (int i = 0; i < 8; i++)
#pragma unroll
        for (int j = 0; j < 8; j++) acc[i][j] = 0.f;

    for (int k0 = 0; k0 < K; k0 += 8) {
        float4 a4 = *(const float4*)(Ag + k0);
        float4 b4 = *(const float4*)(Bg + (size_t)k0 * N);
        As[aCol + 0][aRow] = a4.x;
        As[aCol + 1][aRow] = a4.y;
        As[aCol + 2][aRow] = a4.z;
        As[aCol + 3][aRow] = a4.w;
        *(float4*)&Bs[bRow][bCol] = b4;
        __syncthreads();
#pragma unroll
        for (int kk = 0; kk < 8; kk++) {
            float4 a0 = *(const float4*)&As[kk][trow * 8];
            float4 a1 = *(const float4*)&As[kk][trow * 8 + 4];
            float4 b0 = *(const float4*)&Bs[kk][tcol * 8];
            float4 b1 = *(const float4*)&Bs[kk][tcol * 8 + 4];
            float a[8] = {a0.x, a0.y, a0.z, a0.w, a1.x, a1.y, a1.z, a1.w};
            float b[8] = {b0.x, b0.y, b0.z, b0.w, b1.x, b1.y, b1.z, b1.w};
#pragma unroll
            for (int i = 0; i < 8; i++)
#pragma unroll
                for (int j = 0; j < 8; j++)
                    acc[i][j] = fmaf(a[i], b[j], acc[i][j]);
        }
        __syncthreads();
    }

    const int crow = blockIdx.y * 128 + trow * 8;
    const int ccol = blockIdx.x * 128 + tcol * 8;
    float4 bia0 = *(const float4*)&bias[ccol];
    float4 bia1 = *(const float4*)&bias[ccol + 4];
#pragma unroll
    for (int i = 0; i < 8; i++) {
        float4 o0 = make_float4(acc[i][0] + bia0.x, acc[i][1] + bia0.y,
                                acc[i][2] + bia0.z, acc[i][3] + bia0.w);
        float4 o1 = make_float4(acc[i][4] + bia1.x, acc[i][5] + bia1.y,
                                acc[i][6] + bia1.z, acc[i][7] + bia1.w);
        *(float4*)&C[(size_t)(crow + i) * N + ccol]     = o0;
        *(float4*)&C[(size_t)(crow + i) * N + ccol + 4] = o1;
    }
}

// ---------------------------------------------------------------------------
// Causal flash attention: one block per (q-tile of 64, b*h).
// 256 threads as 16x16 grid; each thread owns a 4x4 micro-tile.
// Shared: Qs[64][64], Kt[64][64] (K transposed: Kt[d][c]), Vs[64][64], Ps[64][64]
// Dynamic smem = 64 KiB (needs opt-in).
// ---------------------------------------------------------------------------
#define ATTN_SMEM (4 * 64 * 64 * (int)sizeof(float))

extern __shared__ float sm_attn[];

__global__ __launch_bounds__(256, 2)
void attn_kernel(const float* __restrict__ qkv, float* __restrict__ y)
{
    float* Qs = sm_attn;            // [64][64]
    float* Kt = Qs + 64 * 64;       // [64][64]  Kt[d][c]
    float* Vs = Kt + 64 * 64;       // [64][64]  Vs[c][d]
    float* Ps = Vs + 64 * 64;       // [64][64]

    const int qt = blockIdx.x;
    const int bh = blockIdx.y;
    const int b  = bh / HH;
    const int h  = bh % HH;
    const int q0 = qt * 64;

    const int tid = threadIdx.x;
    const int ty  = tid >> 4;   // 0..15 -> rows ty*4 .. ty*4+3
    const int tx  = tid & 15;   // 0..15 -> cols tx*4 .. tx*4+3

    // Loader mapping: 4 threads per 64-float row
    const int lr = tid >> 2;    // row 0..63
    const int lq = tid & 3;     // quad 0..3

    const float* base = qkv + (size_t)b * TT * 3 * CC + h * HD;

    // Load Q tile
    {
        const float* qrow = base + (size_t)(q0 + lr) * 3 * CC;
#pragma unroll
        for (int c4 = 0; c4 < 4; c4++) {
            int col = lq * 16 + c4 * 4;
            *(float4*)&Qs[lr * 64 + col] = *(const float4*)(qrow + col);
        }
    }

    float m_i[4], l_i[4], o[4][4];
#pragma unroll
    for (int i = 0; i < 4; i++) {
        m_i[i] = -1e30f;
        l_i[i] = 0.f;
#pragma unroll
        for (int j = 0; j < 4; j++) o[i][j] = 0.f;
    }
    const float scale = 0.125f;  // 1/sqrt(64)

    for (int kt = 0; kt <= qt; kt++) {
        const int k0 = kt * 64;
        __syncthreads();  // protect Qs (1st iter) / Kt,Vs,Ps (later iters)

        // Load K (transposed into Kt[d][c]) and V tiles
        {
            const float* krow = base + (size_t)(k0 + lr) * 3 * CC + CC;
            const float* vrow = krow + CC;
#pragma unroll
            for (int c4 = 0; c4 < 4; c4++) {
                int col = lq * 16 + c4 * 4;
                float4 kv = *(const float4*)(krow + col);
                Kt[(col + 0) * 64 + lr] = kv.x;
                Kt[(col + 1) * 64 + lr] = kv.y;
                Kt[(col + 2) * 64 + lr] = kv.z;
                Kt[(col + 3) * 64 + lr] = kv.w;
                *(float4*)&Vs[lr * 64 + col] = *(const float4*)(vrow + col);
            }
        }
        __syncthreads();

        // S = Q @ K^T  (s[i][j] for rows ty*4+i, cols tx*4+j)
        float s[4][4];
#pragma unroll
        for (int i = 0; i < 4; i++)
#pragma unroll
            for (int j = 0; j < 4; j++) s[i][j] = 0.f;

#pragma unroll 4
        for (int d = 0; d < 64; d += 4) {
            float4 a[4], kb[4];
#pragma unroll
            for (int i = 0; i < 4; i++)
                a[i] = *(const float4*)&Qs[(ty * 4 + i) * 64 + d];
#pragma unroll
            for (int dd = 0; dd < 4; dd++)
                kb[dd] = *(const float4*)&Kt[(d + dd) * 64 + tx * 4];
#pragma unroll
            for (int i = 0; i < 4; i++) {
                s[i][0] += a[i].x * kb[0].x + a[i].y * kb[1].x + a[i].z * kb[2].x + a[i].w * kb[3].x;
                s[i][1] += a[i].x * kb[0].y + a[i].y * kb[1].y + a[i].z * kb[2].y + a[i].w * kb[3].y;
                s[i][2] += a[i].x * kb[0].z + a[i].y * kb[1].z + a[i].z * kb[2].z + a[i].w * kb[3].z;
                s[i][3] += a[i].x * kb[0].w + a[i].y * kb[1].w + a[i].z * kb[2].w + a[i].w * kb[3].w;
            }
        }

        // scale + causal mask (only the diagonal tile can be partially masked)
        const bool diag = (kt == qt);
#pragma unroll
        for (int i = 0; i < 4; i++)
#pragma unroll
            for (int j = 0; j < 4; j++) {
                float v = s[i][j] * scale;
                if (diag && (k0 + tx * 4 + j > q0 + ty * 4 + i)) v = -1e30f;
                s[i][j] = v;
            }

        // online softmax: row reductions across the 16 tx lanes (same ty)
        float rmax[4];
#pragma unroll
        for (int i = 0; i < 4; i++) {
            float v = fmaxf(fmaxf(s[i][0], s[i][1]), fmaxf(s[i][2], s[i][3]));
#pragma unroll
            for (int off = 1; off < 16; off <<= 1)
                v = fmaxf(v, __shfl_xor_sync(0xffffffffu, v, off));
            rmax[i] = v;
        }
        float alpha[4], rsum[4];
#pragma unroll
        for (int i = 0; i < 4; i++) {
            float mn = fmaxf(m_i[i], rmax[i]);
            alpha[i] = __expf(m_i[i] - mn);
            m_i[i] = mn;
            float rs = 0.f;
#pragma unroll
            for (int j = 0; j < 4; j++) {
                float p = __expf(s[i][j] - mn);
                s[i][j] = p;
                rs += p;
            }
            rsum[i] = rs;
        }
#pragma unroll
        for (int i = 0; i < 4; i++) {
#pragma unroll
            for (int off = 1; off < 16; off <<= 1)
                rsum[i] += __shfl_xor_sync(0xffffffffu, rsum[i], off);
            l_i[i] = l_i[i] * alpha[i] + rsum[i];
        }

        // stage P into shared
#pragma unroll
        for (int i = 0; i < 4; i++)
            *(float4*)&Ps[(ty * 4 + i) * 64 + tx * 4] =
                make_float4(s[i][0], s[i][1], s[i][2], s[i][3]);
        __syncthreads();

        // O = O*alpha + P @ V   (cols tx*4+j are d-dims here)
#pragma unroll
        for (int i = 0; i < 4; i++)
#pragma unroll
            for (int j = 0; j < 4; j++) o[i][j] *= alpha[i];

#pragma unroll 4
        for (int c = 0; c < 64; c += 4) {
            float4 pa[4], vv[4];
#pragma unroll
            for (int i = 0; i < 4; i++)
                pa[i] = *(const float4*)&Ps[(ty * 4 + i) * 64 + c];
#pragma unroll
            for (int cc = 0; cc < 4; cc++)
                vv[cc] = *(const float4*)&Vs[(c + cc) * 64 + tx * 4];
#pragma unroll
            for (int i = 0; i < 4; i++) {
                o[i][0] += pa[i].x * vv[0].x + pa[i].y * vv[1].x + pa[i].z * vv[2].x + pa[i].w * vv[3].x;
                o[i][1] += pa[i].x * vv[0].y + pa[i].y * vv[1].y + pa[i].z * vv[2].y + pa[i].w * vv[3].y;
                o[i][2] += pa[i].x * vv[0].z + pa[i].y * vv[1].z + pa[i].z * vv[2].z + pa[i].w * vv[3].z;
                o[i][3] += pa[i].x * vv[0].w + pa[i].y * vv[1].w + pa[i].z * vv[2].w + pa[i].w * vv[3].w;
            }
        }
    }

    // write y[B*T, C]: row q0+ty*4+i, cols h*64 + tx*4 ..
#pragma unroll
    for (int i = 0; i < 4; i++) {
        float inv = 1.0f / l_i[i];
        int rg = q0 + ty * 4 + i;
        float4 out = make_float4(o[i][0] * inv, o[i][1] * inv,
                                 o[i][2] * inv, o[i][3] * inv);
        *(float4*)(y + (size_t)(b * TT + rg) * CC + h * HD + tx * 4) = out;
    }
}

// ---------------------------------------------------------------------------
extern "C" void kernel_launch(void* const* d_in, const int* in_sizes, int n_in,
                              void* d_out, int out_size)
{
    const float* x      = (const float*)d_in[0];
    const float* W_attn = (const float*)d_in[1];
    const float* b_attn = (const float*)d_in[2];
    const float* W_proj = (const float*)d_in[3];
    const float* b_proj = (const float*)d_in[4];
    float* out = (float*)d_out;

    float *qkv, *y;
    cudaGetSymbolAddress((void**)&qkv, g_qkv);
    cudaGetSymbolAddress((void**)&y, g_y);

    cudaFuncSetAttribute(attn_kernel, cudaFuncAttributeMaxDynamicSharedMemorySize,
                         ATTN_SMEM);

    // 1) qkv = x @ W_attn + b_attn   (M=8192, N=3072, K=1024)
    {
        dim3 grid(3 * CC / 128, MR / 128);
        sgemm_bias<<<grid, 256>>>(x, W_attn, b_attn, qkv, MR, 3 * CC, CC);
    }
    // 2) causal flash attention -> y [B*T, C]
    {
        dim3 grid(TT / 64, BB * HH);
        attn_kernel<<<grid, 256, ATTN_SMEM>>>(qkv, y);
    }
    // 3) out = y @ W_proj + b_proj   (M=8192, N=1024, K=1024)
    {
        dim3 grid(CC / 128, MR / 128);
        sgemm_bias<<<grid, 256>>>(y, W_proj, b_proj, out, MR, CC, CC);
    }
}

// round 4
// speedup vs baseline: 1.3724x; 1.3724x over previous
#include <cuda_runtime.h>
#include <cuda_bf16.h>
#include <cstdint>

// Problem constants
#define BB   4
#define TT   2048
#define CC   1024
#define HH   16
#define HD   64
#define MR   (BB*TT)        // 8192 rows

typedef __nv_bfloat16 bf16;

// Scratch (device globals: allocation-free, graph-capturable)
__device__ float g_qkv[(size_t)MR * 3 * CC];          // [B*T, 3C]
__device__ bf16  g_xh[(size_t)MR * CC];               // x hi/lo
__device__ bf16  g_xl[(size_t)MR * CC];
__device__ bf16  g_yh[(size_t)MR * CC];               // attn out hi/lo
__device__ bf16  g_yl[(size_t)MR * CC];
__device__ bf16  g_wah[(size_t)3 * CC * CC];          // W_attn^T hi  [3C][C]
__device__ bf16  g_wal[(size_t)3 * CC * CC];
__device__ bf16  g_wph[(size_t)CC * CC];              // W_proj^T hi  [C][C]
__device__ bf16  g_wpl[(size_t)CC * CC];

// ---------------------------------------------------------------------------
// helpers
// ---------------------------------------------------------------------------
__device__ __forceinline__ uint32_t smem_u32(const void* p) {
    uint32_t a;
    asm("{ .reg .u64 t; cvta.to.shared.u64 t, %1; cvt.u32.u64 %0, t; }"
        : "=r"(a) : "l"(p));
    return a;
}
__device__ __forceinline__ uint32_t pack2(float a, float b) {
    __nv_bfloat162 h = __floats2bfloat162_rn(a, b);
    return *(uint32_t*)&h;
}

#define CPASYNC16(dst, src) \
    asm volatile("cp.async.cg.shared.global [%0], [%1], 16;" \
                 :: "r"(dst), "l"(src) : "memory")
#define CP_COMMIT() asm volatile("cp.async.commit_group;" ::: "memory")
#define CP_WAIT1()  asm volatile("cp.async.wait_group 1;" ::: "memory")
#define CP_WAIT0()  asm volatile("cp.async.wait_group 0;" ::: "memory")

#define LDSM4(r, a) \
    asm volatile("ldmatrix.sync.aligned.m8n8.x4.shared.b16 {%0,%1,%2,%3}, [%4];" \
                 : "=r"((r)[0]), "=r"((r)[1]), "=r"((r)[2]), "=r"((r)[3]) : "r"(a))

#define MMA16816(d, a, b0, b1) \
    asm volatile("mma.sync.aligned.m16n8k16.row.col.f32.bf16.bf16.f32 " \
                 "{%0,%1,%2,%3},{%4,%5,%6,%7},{%8,%9},{%0,%1,%2,%3};" \
                 : "+f"((d)[0]), "+f"((d)[1]), "+f"((d)[2]), "+f"((d)[3]) \
                 : "r"((a)[0]), "r"((a)[1]), "r"((a)[2]), "r"((a)[3]), \
                   "r"(b0), "r"(b1))

// ---------------------------------------------------------------------------
// Weight prep: W [K,N] fp32 -> Wt_hi/Wt_lo [N,K] bf16 (transpose + hi/lo split)
// ---------------------------------------------------------------------------
__global__ __launch_bounds__(256)
void wprep(const float* __restrict__ W, bf16* __restrict__ Wh,
           bf16* __restrict__ Wl, int K, int N)
{
    __shared__ float t[32][33];
    const int k0 = blockIdx.y * 32, n0 = blockIdx.x * 32;
    const int c = threadIdx.x & 31, r = threadIdx.x >> 5;  // r 0..7
#pragma unroll
    for (int p = 0; p < 4; p++)
        t[r + p * 8][c] = W[(size_t)(k0 + r + p * 8) * N + n0 + c];
    __syncthreads();
#pragma unroll
    for (int p = 0; p < 4; p++) {
        float f = t[c][r + p * 8];
        bf16 h = __float2bfloat16(f);
        bf16 l = __float2bfloat16(f - __bfloat162float(h));
        size_t o = (size_t)(n0 + r + p * 8) * K + k0 + c;
        Wh[o] = h;
        Wl[o] = l;
    }
}

// ---------------------------------------------------------------------------
// Elementwise fp32 -> bf16 hi/lo split (for x)
// ---------------------------------------------------------------------------
__global__ __launch_bounds__(256)
void fsplit(const float* __restrict__ A, bf16* __restrict__ Ah,
            bf16* __restrict__ Al, size_t n4)
{
    size_t i = (size_t)blockIdx.x * 256 + threadIdx.x;
    if (i >= n4) return;
    float4 v = *(const float4*)(A + i * 4);
    float f[4] = {v.x, v.y, v.z, v.w};
    uint32_t h0, h1, l0, l1;
    float hh[4];
#pragma unroll
    for (int j = 0; j < 4; j++) hh[j] = __bfloat162float(__float2bfloat16(f[j]));
    h0 = pack2(hh[0], hh[1]); h1 = pack2(hh[2], hh[3]);
    l0 = pack2(f[0] - hh[0], f[1] - hh[1]);
    l1 = pack2(f[2] - hh[2], f[3] - hh[3]);
    ((uint2*)Ah)[i] = make_uint2(h0, h1);
    ((uint2*)Al)[i] = make_uint2(l0, l1);
}

// ---------------------------------------------------------------------------
// bf16x3 GEMM via mma.sync: C[M,N] = A[M,K] @ Wt[N,K]^T + bias
// A given as hi/lo bf16 [M][K]; B as hi/lo bf16 [N][K].
// CTA 128x128, BK=32, 8 warps (4m x 2n), warp tile 32x64.
// SMEM per stage: Ah|Al|Bh|Bl, each 128 rows x 80B (32 bf16 + 16B pad). x2 stages.
// ---------------------------------------------------------------------------
#define TSTRIDE 80
#define TBYTES  (128 * TSTRIDE)          // 10240
#define STAGEB  (4 * TBYTES)             // 40960
#define GSMEM   (2 * STAGEB)             // 81920

extern __shared__ char sm_g[];

__global__ __launch_bounds__(256, 1)
void gemm_mma(const bf16* __restrict__ Ahg, const bf16* __restrict__ Alg,
              const bf16* __restrict__ Bhg, const bf16* __restrict__ Blg,
              const float* __restrict__ bias, float* __restrict__ C,
              int M, int N, int K)
{
    const int tid  = threadIdx.x;
    const int lane = tid & 31;
    const int w    = tid >> 5;
    const int wm   = (w & 3) * 32;   // warp m offset in tile
    const int wn   = (w >> 2) * 64;  // warp n offset in tile
    const int m0 = blockIdx.y * 128;
    const int n0 = blockIdx.x * 128;

    const uint32_t sbase = smem_u32(sm_g);
    const int laneRow  = (lane & 7) | (lane & 8);      // ldmatrix row-in-16
    const int laneKoff = (lane >> 4) << 4;             // 0 or 16 bytes

    float acc[2][8][4];
#pragma unroll
    for (int t = 0; t < 2; t++)
#pragma unroll
        for (int n = 0; n < 8; n++)
#pragma unroll
            for (int j = 0; j < 4; j++) acc[t][n][j] = 0.f;

    const int NCH = K >> 5;   // 32-wide k chunks

    // ---- stage loader: 8 cp.async per thread ----
    auto load_stage = [&](int ch, int s) {
        const uint32_t sb = sbase + (uint32_t)s * STAGEB;
#pragma unroll
        for (int i = 0; i < 2; i++) {
            int idx = i * 256 + tid;
            int r = idx >> 2, c = idx & 3;
            uint32_t dst = sb + (uint32_t)(r * TSTRIDE + c * 16);
            size_t so = (size_t)(m0 + r) * K + ch * 32 + c * 8;
            CPASYNC16(dst,            Ahg + so);
            CPASYNC16(dst + TBYTES,   Alg + so);
        }
#pragma unroll
        for (int i = 0; i < 2; i++) {
            int idx = i * 256 + tid;
            int r = idx >> 2, c = idx & 3;
            uint32_t dst = sb + 2 * TBYTES + (uint32_t)(r * TSTRIDE + c * 16);
            size_t so = (size_t)(n0 + r) * K + ch * 32 + c * 8;
            CPASYNC16(dst,            Bhg + so);
            CPASYNC16(dst + TBYTES,   Blg + so);
        }
    };

    load_stage(0, 0);
    CP_COMMIT();

    for (int ch = 0; ch < NCH; ch++) {
        const int s = ch & 1;
        if (ch + 1 < NCH) {
            load_stage(ch + 1, s ^ 1);
            CP_COMMIT();
            CP_WAIT1();
        } else {
            CP_WAIT0();
        }
        __syncthreads();

        const uint32_t sb = sbase + (uint32_t)s * STAGEB;
#pragma unroll
        for (int ks = 0; ks < 2; ks++) {
            const uint32_t kb = (uint32_t)(ks * 32 + laneKoff);
            uint32_t ah[2][4], al[2][4], bh[4][4], bl[4][4];
#pragma unroll
            for (int t = 0; t < 2; t++) {
                uint32_t ra = sb + (uint32_t)((wm + t * 16 + laneRow) * TSTRIDE) + kb;
                LDSM4(ah[t], ra);
                LDSM4(al[t], ra + TBYTES);
            }
#pragma unroll
            for (int g = 0; g < 4; g++) {
                uint32_t rb = sb + 2 * TBYTES +
                              (uint32_t)((wn + g * 16 + laneRow) * TSTRIDE) + kb;
                LDSM4(bh[g], rb);
                LDSM4(bl[g], rb + TBYTES);
            }
#pragma unroll
            for (int t = 0; t < 2; t++)
#pragma unroll
                for (int g = 0; g < 4; g++) {
                    MMA16816(acc[t][g * 2],     ah[t], bh[g][0], bh[g][2]);
                    MMA16816(acc[t][g * 2],     ah[t], bl[g][0], bl[g][2]);
                    MMA16816(acc[t][g * 2],     al[t], bh[g][0], bh[g][2]);
                    MMA16816(acc[t][g * 2 + 1], ah[t], bh[g][1], bh[g][3]);
                    MMA16816(acc[t][g * 2 + 1], ah[t], bl[g][1], bl[g][3]);
                    MMA16816(acc[t][g * 2 + 1], al[t], bh[g][1], bh[g][3]);
                }
        }
        __syncthreads();
    }

    // ---- epilogue: fragment -> global with bias ----
    const int gr  = lane >> 2;     // row in 8
    const int tig = lane & 3;      // col pair
#pragma unroll
    for (int t = 0; t < 2; t++) {
        int rbase = m0 + wm + t * 16 + gr;
#pragma unroll
        for (int n8 = 0; n8 < 8; n8++) {
            int col = n0 + wn + n8 * 8 + tig * 2;
            float2 bv = *(const float2*)&bias[col];
            float2 v0 = make_float2(acc[t][n8][0] + bv.x, acc[t][n8][1] + bv.y);
            float2 v1 = make_float2(acc[t][n8][2] + bv.x, acc[t][n8][3] + bv.y);
            *(float2*)&C[(size_t)rbase * N + col]       = v0;
            *(float2*)&C[(size_t)(rbase + 8) * N + col] = v1;
        }
    }
}

// ---------------------------------------------------------------------------
// Causal flash attention (SIMT), epilogue writes bf16 hi/lo directly
// ---------------------------------------------------------------------------
#define ATTN_SMEM (4 * 64 * 64 * (int)sizeof(float))

extern __shared__ float sm_attn[];

__global__ __launch_bounds__(256, 2)
void attn_kernel(const float* __restrict__ qkv,
                 bf16* __restrict__ yh, bf16* __restrict__ yl)
{
    float* Qs = sm_attn;
    float* Kt = Qs + 64 * 64;
    float* Vs = Kt + 64 * 64;
    float* Ps = Vs + 64 * 64;

    const int qt = blockIdx.x;
    const int bh = blockIdx.y;
    const int b  = bh / HH;
    const int h  = bh % HH;
    const int q0 = qt * 64;

    const int tid = threadIdx.x;
    const int ty  = tid >> 4;
    const int tx  = tid & 15;
    const int lr = tid >> 2;
    const int lq = tid & 3;

    const float* base = qkv + (size_t)b * TT * 3 * CC + h * HD;

    {
        const float* qrow = base + (size_t)(q0 + lr) * 3 * CC;
#pragma unroll
        for (int c4 = 0; c4 < 4; c4++) {
            int col = lq * 16 + c4 * 4;
            *(float4*)&Qs[lr * 64 + col] = *(const float4*)(qrow + col);
        }
    }

    float m_i[4], l_i[4], o[4][4];
#pragma unroll
    for (int i = 0; i < 4; i++) {
        m_i[i] = -1e30f;
        l_i[i] = 0.f;
#pragma unroll
        for (int j = 0; j < 4; j++) o[i][j] = 0.f;
    }
    const float scale = 0.125f;

    for (int kt = 0; kt <= qt; kt++) {
        const int k0 = kt * 64;
        __syncthreads();

        {
            const float* krow = base + (size_t)(k0 + lr) * 3 * CC + CC;
            const float* vrow = krow + CC;
#pragma unroll
            for (int c4 = 0; c4 < 4; c4++) {
                int col = lq * 16 + c4 * 4;
                float4 kv = *(const float4*)(krow + col);
                Kt[(col + 0) * 64 + lr] = kv.x;
                Kt[(col + 1) * 64 + lr] = kv.y;
                Kt[(col + 2) * 64 + lr] = kv.z;
                Kt[(col + 3) * 64 + lr] = kv.w;
                *(float4*)&Vs[lr * 64 + col] = *(const float4*)(vrow + col);
            }
        }
        __syncthreads();

        float s[4][4];
#pragma unroll
        for (int i = 0; i < 4; i++)
#pragma unroll
            for (int j = 0; j < 4; j++) s[i][j] = 0.f;

#pragma unroll 4
        for (int d = 0; d < 64; d += 4) {
            float4 a[4], kb[4];
#pragma unroll
            for (int i = 0; i < 4; i++)
                a[i] = *(const float4*)&Qs[(ty * 4 + i) * 64 + d];
#pragma unroll
            for (int dd = 0; dd < 4; dd++)
                kb[dd] = *(const float4*)&Kt[(d + dd) * 64 + tx * 4];
#pragma unroll
            for (int i = 0; i < 4; i++) {
                s[i][0] += a[i].x * kb[0].x + a[i].y * kb[1].x + a[i].z * kb[2].x + a[i].w * kb[3].x;
                s[i][1] += a[i].x * kb[0].y + a[i].y * kb[1].y + a[i].z * kb[2].y + a[i].w * kb[3].y;
                s[i][2] += a[i].x * kb[0].z + a[i].y * kb[1].z + a[i].z * kb[2].z + a[i].w * kb[3].z;
                s[i][3] += a[i].x * kb[0].w + a[i].y * kb[1].w + a[i].z * kb[2].w + a[i].w * kb[3].w;
            }
        }

        const bool diag = (kt == qt);
#pragma unroll
        for (int i = 0; i < 4; i++)
#pragma unroll
            for (int j = 0; j < 4; j++) {
                float v = s[i][j] * scale;
                if (diag && (k0 + tx * 4 + j > q0 + ty * 4 + i)) v = -1e30f;
                s[i][j] = v;
            }

        float rmax[4];
#pragma unroll
        for (int i = 0; i < 4; i++) {
            float v = fmaxf(fmaxf(s[i][0], s[i][1]), fmaxf(s[i][2], s[i][3]));
#pragma unroll
            for (int off = 1; off < 16; off <<= 1)
                v = fmaxf(v, __shfl_xor_sync(0xffffffffu, v, off));
            rmax[i] = v;
        }
        float alpha[4], rsum[4];
#pragma unroll
        for (int i = 0; i < 4; i++) {
            float mn = fmaxf(m_i[i], rmax[i]);
            alpha[i] = __expf(m_i[i] - mn);
            m_i[i] = mn;
            float rs = 0.f;
#pragma unroll
            for (int j = 0; j < 4; j++) {
                float p = __expf(s[i][j] - mn);
                s[i][j] = p;
                rs += p;
            }
            rsum[i] = rs;
        }
#pragma unroll
        for (int i = 0; i < 4; i++) {
#pragma unroll
            for (int off = 1; off < 16; off <<= 1)
                rsum[i] += __shfl_xor_sync(0xffffffffu, rsum[i], off);
            l_i[i] = l_i[i] * alpha[i] + rsum[i];
        }

#pragma unroll
        for (int i = 0; i < 4; i++)
            *(float4*)&Ps[(ty * 4 + i) * 64 + tx * 4] =
                make_float4(s[i][0], s[i][1], s[i][2], s[i][3]);
        __syncthreads();

#pragma unroll
        for (int i = 0; i < 4; i++)
#pragma unroll
            for (int j = 0; j < 4; j++) o[i][j] *= alpha[i];

#pragma unroll 4
        for (int c = 0; c < 64; c += 4) {
            float4 pa[4], vv[4];
#pragma unroll
            for (int i = 0; i < 4; i++)
                pa[i] = *(const float4*)&Ps[(ty * 4 + i) * 64 + c];
#pragma unroll
            for (int cc = 0; cc < 4; cc++)
                vv[cc] = *(const float4*)&Vs[(c + cc) * 64 + tx * 4];
#pragma unroll
            for (int i = 0; i < 4; i++) {
                o[i][0] += pa[i].x * vv[0].x + pa[i].y * vv[1].x + pa[i].z * vv[2].x + pa[i].w * vv[3].x;
                o[i][1] += pa[i].x * vv[0].y + pa[i].y * vv[1].y + pa[i].z * vv[2].y + pa[i].w * vv[3].y;
                o[i][2] += pa[i].x * vv[0].z + pa[i].y * vv[1].z + pa[i].z * vv[2].z + pa[i].w * vv[3].z;
                o[i][3] += pa[i].x * vv[0].w + pa[i].y * vv[1].w + pa[i].z * vv[2].w + pa[i].w * vv[3].w;
            }
        }
    }

    // epilogue: normalize, split to bf16 hi/lo, store 8B each
#pragma unroll
    for (int i = 0; i < 4; i++) {
        float inv = 1.0f / l_i[i];
        int rg = q0 + ty * 4 + i;
        float v[4];
#pragma unroll
        for (int j = 0; j < 4; j++) v[j] = o[i][j] * inv;
        float hh[4];
#pragma unroll
        for (int j = 0; j < 4; j++) hh[j] = __bfloat162float(__float2bfloat16(v[j]));
        uint2 hv = make_uint2(pack2(hh[0], hh[1]), pack2(hh[2], hh[3]));
        uint2 lv = make_uint2(pack2(v[0] - hh[0], v[1] - hh[1]),
                              pack2(v[2] - hh[2], v[3] - hh[3]));
        size_t off = (size_t)(b * TT + rg) * CC + h * HD + tx * 4;
        *(uint2*)(yh + off) = hv;
        *(uint2*)(yl + off) = lv;
    }
}

// ---------------------------------------------------------------------------
extern "C" void kernel_launch(void* const* d_in, const int* in_sizes, int n_in,
                              void* d_out, int out_size)
{
    const float* x      = (const float*)d_in[0];
    const float* W_attn = (const float*)d_in[1];
    const float* b_attn = (const float*)d_in[2];
    const float* W_proj = (const float*)d_in[3];
    const float* b_proj = (const float*)d_in[4];
    float* out = (float*)d_out;

    float* qkv;
    bf16 *xh, *xl, *yh, *yl, *wah, *wal, *wph, *wpl;
    cudaGetSymbolAddress((void**)&qkv, g_qkv);
    cudaGetSymbolAddress((void**)&xh, g_xh);
    cudaGetSymbolAddress((void**)&xl, g_xl);
    cudaGetSymbolAddress((void**)&yh, g_yh);
    cudaGetSymbolAddress((void**)&yl, g_yl);
    cudaGetSymbolAddress((void**)&wah, g_wah);
    cudaGetSymbolAddress((void**)&wal, g_wal);
    cudaGetSymbolAddress((void**)&wph, g_wph);
    cudaGetSymbolAddress((void**)&wpl, g_wpl);

    cudaFuncSetAttribute(attn_kernel, cudaFuncAttributeMaxDynamicSharedMemorySize,
                         ATTN_SMEM);
    cudaFuncSetAttribute(gemm_mma, cudaFuncAttributeMaxDynamicSharedMemorySize,
                         GSMEM);

    // 0) weight transpose+split, x split
    wprep<<<dim3(3 * CC / 32, CC / 32), 256>>>(W_attn, wah, wal, CC, 3 * CC);
    wprep<<<dim3(CC / 32, CC / 32), 256>>>(W_proj, wph, wpl, CC, CC);
    {
        size_t n4 = (size_t)MR * CC / 4;
        fsplit<<<(unsigned)((n4 + 255) / 256), 256>>>(x, xh, xl, n4);
    }

    // 1) qkv = x @ W_attn + b_attn   (M=8192, N=3072, K=1024)
    gemm_mma<<<dim3(3 * CC / 128, MR / 128), 256, GSMEM>>>(
        xh, xl, wah, wal, b_attn, qkv, MR, 3 * CC, CC);

    // 2) causal flash attention -> yh/yl (bf16 split)
    attn_kernel<<<dim3(TT / 64, BB * HH), 256, ATTN_SMEM>>>(qkv, yh, yl);

    // 3) out = y @ W_proj + b_proj   (M=8192, N=1024, K=1024)
    gemm_mma<<<dim3(CC / 128, MR / 128), 256, GSMEM>>>(
        yh, yl, wph, wpl, b_proj, out, MR, CC, CC);
}

// round 6
// speedup vs baseline: 2.8237x; 2.0575x over previous
#include <cuda_runtime.h>
#include <cuda_bf16.h>
#include <cstdint>

#define BB   4
#define TT   2048
#define CC   1024
#define HH   16
#define HD   64
#define MR   (BB*TT)

typedef __nv_bfloat16 bf16;

// Scratch (device globals)
__device__ bf16  g_qkvh[(size_t)MR * 3 * CC];   // qkv hi [B*T, 3C]
__device__ bf16  g_qkvl[(size_t)MR * 3 * CC];   // qkv lo
__device__ bf16  g_xh[(size_t)MR * CC];
__device__ bf16  g_xl[(size_t)MR * CC];
__device__ bf16  g_yh[(size_t)MR * CC];
__device__ bf16  g_yl[(size_t)MR * CC];
__device__ bf16  g_wah[(size_t)3 * CC * CC];
__device__ bf16  g_wal[(size_t)3 * CC * CC];
__device__ bf16  g_wph[(size_t)CC * CC];
__device__ bf16  g_wpl[(size_t)CC * CC];

// ---------------------------------------------------------------------------
__device__ __forceinline__ uint32_t smem_u32(const void* p) {
    uint32_t a;
    asm("{ .reg .u64 t; cvta.to.shared.u64 t, %1; cvt.u32.u64 %0, t; }"
        : "=r"(a) : "l"(p));
    return a;
}
__device__ __forceinline__ uint32_t pack2(float a, float b) {
    __nv_bfloat162 h = __floats2bfloat162_rn(a, b);
    return *(uint32_t*)&h;
}
__device__ __forceinline__ void split2(float a, float b, uint32_t& ph, uint32_t& pl) {
    float ha = __bfloat162float(__float2bfloat16(a));
    float hb = __bfloat162float(__float2bfloat16(b));
    ph = pack2(ha, hb);
    pl = pack2(a - ha, b - hb);
}
#define SWZ(x) ((x) ^ (((x) >> 3) & 0x70))

#define CPASYNC16(dst, src) \
    asm volatile("cp.async.cg.shared.global [%0], [%1], 16;" \
                 :: "r"(dst), "l"(src) : "memory")
#define CP_COMMIT() asm volatile("cp.async.commit_group;" ::: "memory")
#define CP_WAIT1()  asm volatile("cp.async.wait_group 1;" ::: "memory")
#define CP_WAIT0()  asm volatile("cp.async.wait_group 0;" ::: "memory")

#define LDSM4(r, a) \
    asm volatile("ldmatrix.sync.aligned.m8n8.x4.shared.b16 {%0,%1,%2,%3}, [%4];" \
                 : "=r"((r)[0]), "=r"((r)[1]), "=r"((r)[2]), "=r"((r)[3]) : "r"(a))
#define LDSM4T(r, a) \
    asm volatile("ldmatrix.sync.aligned.m8n8.x4.trans.shared.b16 {%0,%1,%2,%3}, [%4];" \
                 : "=r"((r)[0]), "=r"((r)[1]), "=r"((r)[2]), "=r"((r)[3]) : "r"(a))

#define MMA16816(d, a, b0, b1) \
    asm volatile("mma.sync.aligned.m16n8k16.row.col.f32.bf16.bf16.f32 " \
                 "{%0,%1,%2,%3},{%4,%5,%6,%7},{%8,%9},{%0,%1,%2,%3};" \
                 : "+f"((d)[0]), "+f"((d)[1]), "+f"((d)[2]), "+f"((d)[3]) \
                 : "r"((a)[0]), "r"((a)[1]), "r"((a)[2]), "r"((a)[3]), \
                   "r"(b0), "r"(b1))

// ---------------------------------------------------------------------------
// Weight prep: W [K,N] fp32 -> Wt_hi/Wt_lo [N,K] bf16
// ---------------------------------------------------------------------------
__global__ __launch_bounds__(256)
void wprep(const float* __restrict__ W, bf16* __restrict__ Wh,
           bf16* __restrict__ Wl, int K, int N)
{
    __shared__ float t[32][33];
    const int k0 = blockIdx.y * 32, n0 = blockIdx.x * 32;
    const int c = threadIdx.x & 31, r = threadIdx.x >> 5;
#pragma unroll
    for (int p = 0; p < 4; p++)
        t[r + p * 8][c] = W[(size_t)(k0 + r + p * 8) * N + n0 + c];
    __syncthreads();
#pragma unroll
    for (int p = 0; p < 4; p++) {
        float f = t[c][r + p * 8];
        bf16 h = __float2bfloat16(f);
        bf16 l = __float2bfloat16(f - __bfloat162float(h));
        size_t o = (size_t)(n0 + r + p * 8) * K + k0 + c;
        Wh[o] = h;
        Wl[o] = l;
    }
}

__global__ __launch_bounds__(256)
void fsplit(const float* __restrict__ A, bf16* __restrict__ Ah,
            bf16* __restrict__ Al, size_t n4)
{
    size_t i = (size_t)blockIdx.x * 256 + threadIdx.x;
    if (i >= n4) return;
    float4 v = *(const float4*)(A + i * 4);
    float f[4] = {v.x, v.y, v.z, v.w};
    uint32_t h0, h1, l0, l1;
    split2(f[0], f[1], h0, l0);
    split2(f[2], f[3], h1, l1);
    ((uint2*)Ah)[i] = make_uint2(h0, h1);
    ((uint2*)Al)[i] = make_uint2(l0, l1);
}

// ---------------------------------------------------------------------------
// bf16x3 GEMM via mma.sync.  Output either fp32 (C) or split bf16 (Ch/Cl).
// CTA 128x128, BK=32, 8 warps (4m x 2n), double-buffered cp.async.
// ---------------------------------------------------------------------------
#define TSTRIDE 80
#define TBYTES  (128 * TSTRIDE)
#define STAGEB  (4 * TBYTES)
#define GSMEM   (2 * STAGEB)

extern __shared__ char sm_g[];

__global__ __launch_bounds__(256, 2)
void gemm_mma(const bf16* __restrict__ Ahg, const bf16* __restrict__ Alg,
              const bf16* __restrict__ Bhg, const bf16* __restrict__ Blg,
              const float* __restrict__ bias, float* __restrict__ C,
              bf16* __restrict__ Ch, bf16* __restrict__ Cl,
              int M, int N, int K)
{
    const int tid  = threadIdx.x;
    const int lane = tid & 31;
    const int w    = tid >> 5;
    const int wm   = (w & 3) * 32;
    const int wn   = (w >> 2) * 64;
    const int m0 = blockIdx.y * 128;
    const int n0 = blockIdx.x * 128;

    const uint32_t sbase = smem_u32(sm_g);
    const int laneRow  = lane & 15;
    const int laneKoff = (lane >> 4) << 4;

    float acc[2][8][4];
#pragma unroll
    for (int t = 0; t < 2; t++)
#pragma unroll
        for (int n = 0; n < 8; n++)
#pragma unroll
            for (int j = 0; j < 4; j++) acc[t][n][j] = 0.f;

    const int NCH = K >> 5;

    auto load_stage = [&](int ch, int s) {
        const uint32_t sb = sbase + (uint32_t)s * STAGEB;
#pragma unroll
        for (int i = 0; i < 2; i++) {
            int idx = i * 256 + tid;
            int r = idx >> 2, c = idx & 3;
            uint32_t dst = sb + (uint32_t)(r * TSTRIDE + c * 16);
            size_t so = (size_t)(m0 + r) * K + ch * 32 + c * 8;
            CPASYNC16(dst,          Ahg + so);
            CPASYNC16(dst + TBYTES, Alg + so);
        }
#pragma unroll
        for (int i = 0; i < 2; i++) {
            int idx = i * 256 + tid;
            int r = idx >> 2, c = idx & 3;
            uint32_t dst = sb + 2 * TBYTES + (uint32_t)(r * TSTRIDE + c * 16);
            size_t so = (size_t)(n0 + r) * K + ch * 32 + c * 8;
            CPASYNC16(dst,          Bhg + so);
            CPASYNC16(dst + TBYTES, Blg + so);
        }
    };

    load_stage(0, 0);
    CP_COMMIT();

    for (int ch = 0; ch < NCH; ch++) {
        const int s = ch & 1;
        if (ch + 1 < NCH) {
            load_stage(ch + 1, s ^ 1);
            CP_COMMIT();
            CP_WAIT1();
        } else {
            CP_WAIT0();
        }
        __syncthreads();

        const uint32_t sb = sbase + (uint32_t)s * STAGEB;
#pragma unroll
        for (int ks = 0; ks < 2; ks++) {
            const uint32_t kb = (uint32_t)(ks * 32 + laneKoff);
            uint32_t ah[2][4], al[2][4], bh[4][4], bl[4][4];
#pragma unroll
            for (int t = 0; t < 2; t++) {
                uint32_t ra = sb + (uint32_t)((wm + t * 16 + laneRow) * TSTRIDE) + kb;
                LDSM4(ah[t], ra);
                LDSM4(al[t], ra + TBYTES);
            }
#pragma unroll
            for (int g = 0; g < 4; g++) {
                uint32_t rb = sb + 2 * TBYTES +
                              (uint32_t)((wn + g * 16 + laneRow) * TSTRIDE) + kb;
                LDSM4(bh[g], rb);
                LDSM4(bl[g], rb + TBYTES);
            }
#pragma unroll
            for (int t = 0; t < 2; t++)
#pragma unroll
                for (int g = 0; g < 4; g++) {
                    MMA16816(acc[t][g * 2],     ah[t], bh[g][0], bh[g][2]);
                    MMA16816(acc[t][g * 2],     ah[t], bl[g][0], bl[g][2]);
                    MMA16816(acc[t][g * 2],     al[t], bh[g][0], bh[g][2]);
                    MMA16816(acc[t][g * 2 + 1], ah[t], bh[g][1], bh[g][3]);
                    MMA16816(acc[t][g * 2 + 1], ah[t], bl[g][1], bl[g][3]);
                    MMA16816(acc[t][g * 2 + 1], al[t], bh[g][1], bh[g][3]);
                }
        }
        __syncthreads();
    }

    const int gr  = lane >> 2;
    const int tig = lane & 3;
#pragma unroll
    for (int t = 0; t < 2; t++) {
        int rbase = m0 + wm + t * 16 + gr;
#pragma unroll
        for (int n8 = 0; n8 < 8; n8++) {
            int col = n0 + wn + n8 * 8 + tig * 2;
            float2 bv = *(const float2*)&bias[col];
            float v0 = acc[t][n8][0] + bv.x, v1 = acc[t][n8][1] + bv.y;
            float v2 = acc[t][n8][2] + bv.x, v3 = acc[t][n8][3] + bv.y;
            if (Ch) {
                uint32_t h0, l0, h1, l1;
                split2(v0, v1, h0, l0);
                split2(v2, v3, h1, l1);
                *(uint32_t*)(Ch + (size_t)rbase * N + col)       = h0;
                *(uint32_t*)(Cl + (size_t)rbase * N + col)       = l0;
                *(uint32_t*)(Ch + (size_t)(rbase + 8) * N + col) = h1;
                *(uint32_t*)(Cl + (size_t)(rbase + 8) * N + col) = l1;
            } else {
                *(float2*)(C + (size_t)rbase * N + col)       = make_float2(v0, v1);
                *(float2*)(C + (size_t)(rbase + 8) * N + col) = make_float2(v2, v3);
            }
        }
    }
}

// ---------------------------------------------------------------------------
// Flash attention via mma.sync, bf16x3 for both S=QK^T and O=PV.
// 128 threads (4 warps); warp w owns q-rows 16w..16w+15 of a 64-row tile.
// SMEM: Qh|Ql (8KB each) + 2 stages of Kh|Kl|Vh|Vl (8KB each).
// ---------------------------------------------------------------------------
#define ASTAGE (4 * 8192)
#define ATTN_SMEM (16384 + 2 * ASTAGE)   // 81920

extern __shared__ char sm_a[];

__global__ __launch_bounds__(128, 2)
void attn_mma(const bf16* __restrict__ qkvh, const bf16* __restrict__ qkvl,
              bf16* __restrict__ yh, bf16* __restrict__ yl)
{
    const int qt = blockIdx.x, bhx = blockIdx.y;
    const int b = bhx / HH, h = bhx % HH;
    const int q0 = qt * 64;
    const int tid = threadIdx.x, lane = tid & 31, w = tid >> 5;

    const uint32_t sQh = smem_u32(sm_a);
    const uint32_t sQl = sQh + 8192;
    const uint32_t sSt = sQh + 16384;
    const int laneRow  = lane & 15;
    const int laneKoff = (lane >> 4) << 4;

    const size_t rowbase = (size_t)b * TT * 3 * CC;
    const int hc = h * HD;

    // ---- Q tile load (hi/lo) ----
    {
        int r = tid >> 3, c = tid & 7;
#pragma unroll
        for (int rr = 0; rr < 4; rr++) {
            int row = rr * 16 + r;
            uint32_t doff = SWZ((uint32_t)(row * 128 + c * 16));
            size_t src = rowbase + (size_t)(q0 + row) * 3 * CC + hc + c * 8;
            CPASYNC16(sQh + doff, qkvh + src);
            CPASYNC16(sQl + doff, qkvl + src);
        }
    }
    // ---- KV stage loader ----
    auto load_kv = [&](int kt, int s) {
        uint32_t sb = sSt + (uint32_t)s * ASTAGE;
        int r = tid >> 3, c = tid & 7;
#pragma unroll
        for (int rr = 0; rr < 4; rr++) {
            int row = rr * 16 + r;
            uint32_t doff = SWZ((uint32_t)(row * 128 + c * 16));
            size_t grow = rowbase + (size_t)(kt * 64 + row) * 3 * CC + c * 8;
            CPASYNC16(sb + doff,         qkvh + grow + CC + hc);
            CPASYNC16(sb + 8192 + doff,  qkvl + grow + CC + hc);
            CPASYNC16(sb + 16384 + doff, qkvh + grow + 2 * CC + hc);
            CPASYNC16(sb + 24576 + doff, qkvl + grow + 2 * CC + hc);
        }
    };

    load_kv(0, 0);
    CP_COMMIT();
    CP_WAIT0();
    __syncthreads();

    // ---- Q fragments ----
    uint32_t qh[4][4], ql[4][4];
#pragma unroll
    for (int kc = 0; kc < 4; kc++) {
        uint32_t ra = SWZ((uint32_t)((16 * w + laneRow) * 128 + kc * 32 + laneKoff));
        LDSM4(qh[kc], sQh + ra);
        LDSM4(ql[kc], sQl + ra);
    }

    float o[8][4];
#pragma unroll
    for (int j = 0; j < 8; j++)
#pragma unroll
        for (int e = 0; e < 4; e++) o[j][e] = 0.f;
    float m0 = -1e30f, m1 = -1e30f, l0 = 0.f, l1 = 0.f;

    const int r0 = lane >> 2, i2 = (lane & 3) * 2;

    for (int kt = 0; kt <= qt; kt++) {
        const int s = kt & 1;
        if (kt < qt) {
            load_kv(kt + 1, s ^ 1);
            CP_COMMIT();
            CP_WAIT1();
        } else {
            CP_WAIT0();
        }
        __syncthreads();
        const uint32_t sb = sSt + (uint32_t)s * ASTAGE;

        // ---- S = Qh*Kh + Qh*Kl + Ql*Kh ----
        float sc[8][4];
#pragma unroll
        for (int j = 0; j < 8; j++)
#pragma unroll
            for (int e = 0; e < 4; e++) sc[j][e] = 0.f;
#pragma unroll
        for (int g = 0; g < 4; g++)
#pragma unroll
            for (int kc = 0; kc < 4; kc++) {
                uint32_t rb = sb + SWZ((uint32_t)((g * 16 + laneRow) * 128 + kc * 32 + laneKoff));
                uint32_t kh[4], kl[4];
                LDSM4(kh, rb);
                LDSM4(kl, rb + 8192);
                MMA16816(sc[2 * g],     qh[kc], kh[0], kh[2]);
                MMA16816(sc[2 * g],     qh[kc], kl[0], kl[2]);
                MMA16816(sc[2 * g],     ql[kc], kh[0], kh[2]);
                MMA16816(sc[2 * g + 1], qh[kc], kh[1], kh[3]);
                MMA16816(sc[2 * g + 1], qh[kc], kl[1], kl[3]);
                MMA16816(sc[2 * g + 1], ql[kc], kh[1], kh[3]);
            }

        // ---- scale + causal mask ----
        const float scale = 0.125f;
        if (kt == qt) {
            int rowa = 16 * w + r0, rowb = rowa + 8;
#pragma unroll
            for (int j = 0; j < 8; j++) {
#pragma unroll
                for (int e = 0; e < 2; e++) {
                    int col = j * 8 + i2 + e;
                    sc[j][e]     = (col <= rowa) ? sc[j][e] * scale     : -1e30f;
                    sc[j][2 + e] = (col <= rowb) ? sc[j][2 + e] * scale : -1e30f;
                }
            }
        } else {
#pragma unroll
            for (int j = 0; j < 8; j++)
#pragma unroll
                for (int e = 0; e < 4; e++) sc[j][e] *= scale;
        }

        // ---- online softmax ----
        float mx0 = -1e30f, mx1 = -1e30f;
#pragma unroll
        for (int j = 0; j < 8; j++) {
            mx0 = fmaxf(mx0, fmaxf(sc[j][0], sc[j][1]));
            mx1 = fmaxf(mx1, fmaxf(sc[j][2], sc[j][3]));
        }
#pragma unroll
        for (int off = 1; off < 4; off <<= 1) {
            mx0 = fmaxf(mx0, __shfl_xor_sync(0xffffffffu, mx0, off));
            mx1 = fmaxf(mx1, __shfl_xor_sync(0xffffffffu, mx1, off));
        }
        float mn0 = fmaxf(m0, mx0), mn1 = fmaxf(m1, mx1);
        float al0 = __expf(m0 - mn0), al1 = __expf(m1 - mn1);
        m0 = mn0; m1 = mn1;
        float sum0 = 0.f, sum1 = 0.f;
#pragma unroll
        for (int j = 0; j < 8; j++) {
            sc[j][0] = __expf(sc[j][0] - mn0);
            sc[j][1] = __expf(sc[j][1] - mn0);
            sc[j][2] = __expf(sc[j][2] - mn1);
            sc[j][3] = __expf(sc[j][3] - mn1);
            sum0 += sc[j][0] + sc[j][1];
            sum1 += sc[j][2] + sc[j][3];
        }
#pragma unroll
        for (int off = 1; off < 4; off <<= 1) {
            sum0 += __shfl_xor_sync(0xffffffffu, sum0, off);
            sum1 += __shfl_xor_sync(0xffffffffu, sum1, off);
        }
        l0 = l0 * al0 + sum0;
        l1 = l1 * al1 + sum1;
#pragma unroll
        for (int j = 0; j < 8; j++) {
            o[j][0] *= al0; o[j][1] *= al0;
            o[j][2] *= al1; o[j][3] *= al1;
        }

        // ---- P fragments (hi/lo), accumulator reinterpreted as A-frag ----
        uint32_t ph[4][4], pl[4][4];
#pragma unroll
        for (int kc = 0; kc < 4; kc++) {
            split2(sc[2 * kc][0],     sc[2 * kc][1],     ph[kc][0], pl[kc][0]);
            split2(sc[2 * kc][2],     sc[2 * kc][3],     ph[kc][1], pl[kc][1]);
            split2(sc[2 * kc + 1][0], sc[2 * kc + 1][1], ph[kc][2], pl[kc][2]);
            split2(sc[2 * kc + 1][2], sc[2 * kc + 1][3], ph[kc][3], pl[kc][3]);
        }

        // ---- O += Ph*Vh + Ph*Vl + Pl*Vh  (V via ldmatrix.trans) ----
#pragma unroll
        for (int kc = 0; kc < 4; kc++)
#pragma unroll
            for (int dg = 0; dg < 4; dg++) {
                uint32_t rv = sb + 16384 +
                              SWZ((uint32_t)((kc * 16 + laneRow) * 128 + dg * 32 + laneKoff));
                uint32_t vh[4], vl[4];
                LDSM4T(vh, rv);
                LDSM4T(vl, rv + 8192);
                MMA16816(o[2 * dg],     ph[kc], vh[0], vh[1]);
                MMA16816(o[2 * dg],     ph[kc], vl[0], vl[1]);
                MMA16816(o[2 * dg],     pl[kc], vh[0], vh[1]);
                MMA16816(o[2 * dg + 1], ph[kc], vh[2], vh[3]);
                MMA16816(o[2 * dg + 1], ph[kc], vl[2], vl[3]);
                MMA16816(o[2 * dg + 1], pl[kc], vh[2], vh[3]);
            }
        __syncthreads();
    }

    // ---- epilogue ----
    float inv0 = 1.0f / l0, inv1 = 1.0f / l1;
    size_t ra = (size_t)(b * TT + q0 + 16 * w + r0) * CC + hc;
    size_t rb = ra + (size_t)8 * CC;
#pragma unroll
    for (int j = 0; j < 8; j++) {
        int col = j * 8 + i2;
        uint32_t h0, lo0, h1, lo1;
        split2(o[j][0] * inv0, o[j][1] * inv0, h0, lo0);
        split2(o[j][2] * inv1, o[j][3] * inv1, h1, lo1);
        *(uint32_t*)(yh + ra + col) = h0;
        *(uint32_t*)(yl + ra + col) = lo0;
        *(uint32_t*)(yh + rb + col) = h1;
        *(uint32_t*)(yl + rb + col) = lo1;
    }
}

// ---------------------------------------------------------------------------
extern "C" void kernel_launch(void* const* d_in, const int* in_sizes, int n_in,
                              void* d_out, int out_size)
{
    const float* x      = (const float*)d_in[0];
    const float* W_attn = (const float*)d_in[1];
    const float* b_attn = (const float*)d_in[2];
    const float* W_proj = (const float*)d_in[3];
    const float* b_proj = (const float*)d_in[4];
    float* out = (float*)d_out;

    bf16 *qkvh, *qkvl, *xh, *xl, *yh, *yl, *wah, *wal, *wph, *wpl;
    cudaGetSymbolAddress((void**)&qkvh, g_qkvh);
    cudaGetSymbolAddress((void**)&qkvl, g_qkvl);
    cudaGetSymbolAddress((void**)&xh, g_xh);
    cudaGetSymbolAddress((void**)&xl, g_xl);
    cudaGetSymbolAddress((void**)&yh, g_yh);
    cudaGetSymbolAddress((void**)&yl, g_yl);
    cudaGetSymbolAddress((void**)&wah, g_wah);
    cudaGetSymbolAddress((void**)&wal, g_wal);
    cudaGetSymbolAddress((void**)&wph, g_wph);
    cudaGetSymbolAddress((void**)&wpl, g_wpl);

    cudaFuncSetAttribute(gemm_mma, cudaFuncAttributeMaxDynamicSharedMemorySize, GSMEM);
    cudaFuncSetAttribute(attn_mma, cudaFuncAttributeMaxDynamicSharedMemorySize, ATTN_SMEM);

    // 0) weight prep + x split
    wprep<<<dim3(3 * CC / 32, CC / 32), 256>>>(W_attn, wah, wal, CC, 3 * CC);
    wprep<<<dim3(CC / 32, CC / 32), 256>>>(W_proj, wph, wpl, CC, CC);
    {
        size_t n4 = (size_t)MR * CC / 4;
        fsplit<<<(unsigned)((n4 + 255) / 256), 256>>>(x, xh, xl, n4);
    }

    // 1) qkv (split bf16 out) = x @ W_attn + b_attn
    gemm_mma<<<dim3(3 * CC / 128, MR / 128), 256, GSMEM>>>(
        xh, xl, wah, wal, b_attn, nullptr, qkvh, qkvl, MR, 3 * CC, CC);

    // 2) flash attention (tensor) -> yh/yl
    attn_mma<<<dim3(TT / 64, BB * HH), 128, ATTN_SMEM>>>(qkvh, qkvl, yh, yl);

    // 3) out = y @ W_proj + b_proj (fp32 out)
    gemm_mma<<<dim3(CC / 128, MR / 128), 256, GSMEM>>>(
        yh, yl, wph, wpl, b_proj, out, nullptr, nullptr, MR, CC, CC);
}